// round 5
// baseline (speedup 1.0000x reference)
#include <cuda_runtime.h>
#include <cstdint>
#include <math.h>

// Problem constants
#define B_    4
#define NTOK  1032
#define C_    1024
#define H_    16
#define HD    64
#define BH    64            // B_*H_
#define M_ALL 4128          // B_*NTOK
#define SCALE 0.125f        // HD^-0.5
#define W_SOFT 0.8f         // TAU*(1-LAMBDA)
#define W_RCS  1.2f         // TAU*LAMBDA

#define LDA 20              // proj/kv kernels: BK(16) + 4 pad

// Fused-attention smem layout (float words)
#define LDK 68
#define LDV 72
#define LDR 132
#define SM_KM 0
#define SM_KN 8704
#define SM_VS 17408
#define SM_RB 26624
#define SMEM_WORDS 43520    // 174080 bytes

// Scratch
__device__ float g_K[BH * NTOK * HD];            // [bh][tok][d]
__device__ float g_V[BH * NTOK * HD];            // [bh][tok][d]
__device__ float g_O[(size_t)M_ALL * C_];        // [b*n][c]

__device__ __forceinline__ unsigned f2tf(float f) {
    unsigned u; asm("cvt.rna.tf32.f32 %0, %1;" : "=r"(u) : "f"(f)); return u;
}
__device__ __forceinline__ void mma_tf32(float* c, unsigned a0, unsigned a1,
                                         unsigned a2, unsigned a3,
                                         unsigned b0, unsigned b1) {
    asm volatile(
        "mma.sync.aligned.m16n8k8.row.col.f32.tf32.tf32.f32 "
        "{%0,%1,%2,%3},{%4,%5,%6,%7},{%8,%9},{%0,%1,%2,%3};"
        : "+f"(c[0]), "+f"(c[1]), "+f"(c[2]), "+f"(c[3])
        : "r"(a0), "r"(a1), "r"(a2), "r"(a3), "r"(b0), "r"(b1));
}
__device__ __forceinline__ void cpasync16(uint32_t dst, const void* src, int sbytes) {
    asm volatile("cp.async.cg.shared.global [%0], [%1], 16, %2;"
                 :: "r"(dst), "l"(src), "r"(sbytes));
}

// ---------------------------------------------------------------------------
// Kernel 1: K,V projection (tf32 mma).
// ---------------------------------------------------------------------------
__global__ __launch_bounds__(256) void kv_proj_kernel(
    const float* __restrict__ x, const float* __restrict__ qkv_w,
    const float* __restrict__ qkv_b)
{
    __shared__ unsigned As[128 * LDA];
    __shared__ unsigned Bs[128 * LDA];
    const int tid = threadIdx.x;
    const int m0 = blockIdx.y * 128, j0 = blockIdx.x * 128;
    const int wid = tid >> 5, lane = tid & 31;
    const int g = lane >> 2, t = lane & 3;
    const int wm = (wid >> 2) * 64, wn = (wid & 3) * 32;
    const int lrow = tid >> 1, lcol = (tid & 1) * 8;
    const float* Wk = qkv_w + (size_t)C_ * C_;

    float acc[4][4][4];
#pragma unroll
    for (int a = 0; a < 4; a++)
#pragma unroll
        for (int b = 0; b < 4; b++)
#pragma unroll
            for (int c = 0; c < 4; c++) acc[a][b][c] = 0.f;

    for (int k0 = 0; k0 < C_; k0 += 16) {
        float4 v0, v1;
        if (m0 + lrow < M_ALL) {
            const float* p = x + (size_t)(m0 + lrow) * C_ + k0 + lcol;
            v0 = *(const float4*)p; v1 = *(const float4*)(p + 4);
        } else { v0 = make_float4(0,0,0,0); v1 = v0; }
        unsigned* a = As + lrow * LDA + lcol;
        a[0]=f2tf(v0.x); a[1]=f2tf(v0.y); a[2]=f2tf(v0.z); a[3]=f2tf(v0.w);
        a[4]=f2tf(v1.x); a[5]=f2tf(v1.y); a[6]=f2tf(v1.z); a[7]=f2tf(v1.w);

        const float* q = Wk + (size_t)(j0 + lrow) * C_ + k0 + lcol;
        v0 = *(const float4*)q; v1 = *(const float4*)(q + 4);
        unsigned* bsp = Bs + lrow * LDA + lcol;
        bsp[0]=f2tf(v0.x); bsp[1]=f2tf(v0.y); bsp[2]=f2tf(v0.z); bsp[3]=f2tf(v0.w);
        bsp[4]=f2tf(v1.x); bsp[5]=f2tf(v1.y); bsp[6]=f2tf(v1.z); bsp[7]=f2tf(v1.w);
        __syncthreads();

#pragma unroll
        for (int ks = 0; ks < 16; ks += 8) {
            unsigned af[4][4], bf[4][2];
#pragma unroll
            for (int mt = 0; mt < 4; mt++) {
                const unsigned* ap = As + (wm + mt*16 + g) * LDA + ks + t;
                af[mt][0]=ap[0]; af[mt][1]=ap[8*LDA]; af[mt][2]=ap[4]; af[mt][3]=ap[8*LDA+4];
            }
#pragma unroll
            for (int nt = 0; nt < 4; nt++) {
                const unsigned* bp = Bs + (wn + nt*8 + g) * LDA + ks + t;
                bf[nt][0]=bp[0]; bf[nt][1]=bp[4];
            }
#pragma unroll
            for (int mt = 0; mt < 4; mt++)
#pragma unroll
                for (int nt = 0; nt < 4; nt++)
                    mma_tf32(acc[mt][nt], af[mt][0],af[mt][1],af[mt][2],af[mt][3],
                             bf[nt][0], bf[nt][1]);
        }
        __syncthreads();
    }

#pragma unroll
    for (int mt = 0; mt < 4; mt++) {
#pragma unroll
        for (int h = 0; h < 2; h++) {
            int m = m0 + wm + mt*16 + g + h*8;
            if (m >= M_ALL) continue;
            int b = m / NTOK, n = m - b * NTOK;
#pragma unroll
            for (int nt = 0; nt < 4; nt++) {
                int j = j0 + wn + nt*8 + t*2;
#pragma unroll
                for (int c = 0; c < 2; c++) {
                    int jj = j + c;
                    float v = acc[mt][nt][h*2 + c] + qkv_b[C_ + jj];
                    if (jj < C_) {
                        int hh = jj >> 6, d = jj & 63;
                        g_K[(((size_t)b*H_ + hh)*NTOK + n)*HD + d] = v;
                    } else {
                        int j2 = jj - C_;
                        int hh = j2 >> 6, d = j2 & 63;
                        g_V[(((size_t)b*H_ + hh)*NTOK + n)*HD + d] = v;
                    }
                }
            }
        }
    }
}

// ---------------------------------------------------------------------------
// Kernel 2: fused attention. One block = (bh, 128 m-rows). 8 warps, each owns
// 16 m-rows. Loop over 9 n-tiles of 128:
//   GEMM1: S = Km·Kn^T (per-warp 16x128, accS in regs)
//   epilogue: P = exp(scale*S + add), rowsum partials in regs
//   GEMM2/3 fused: accP += P@V (shuffle C->A), accR += rcs@V (rcs via cp.async)
// Final: out = accP * (0.8/rowsum) + 1.2*accR  -> g_O
// ---------------------------------------------------------------------------
__global__ __launch_bounds__(256, 1) void attn_fused_kernel(
    const float* __restrict__ addn, const float* __restrict__ rcs)
{
    extern __shared__ float sm[];
    float* Km = sm + SM_KM;
    float* Kn = sm + SM_KN;
    float* Vs = sm + SM_VS;
    float* Rb = sm + SM_RB;
    const int tid = threadIdx.x;
    const int bh = blockIdx.y;
    const int b = bh >> 4, hh = bh & 15;
    const int m0 = blockIdx.x * 128;
    const int wid = tid >> 5, lane = tid & 31;
    const int g = lane >> 2, t = lane & 3;
    const int r0 = wid * 16 + g;
    const int r1 = r0 + 8;
    const int gm0 = m0 + r0, gm1 = m0 + r1;
    const float* Kbh = g_K + (size_t)bh * NTOK * HD;
    const float* Vbh = g_V + (size_t)bh * NTOK * HD;
    const float* Rbh = rcs + (size_t)bh * NTOK * NTOK;

    const uint32_t smem_u32 = (uint32_t)__cvta_generic_to_shared(sm);

    // Load Km (this block's 128 K rows), once.
#pragma unroll
    for (int i = 0; i < 8; i++) {
        int c = tid + i * 256;
        int row = c >> 4, ch = (c & 15) * 4;
        float4 v = make_float4(0.f, 0.f, 0.f, 0.f);
        if (m0 + row < NTOK)
            v = *(const float4*)(Kbh + (size_t)(m0 + row) * HD + ch);
        *(float4*)(Km + row * LDK + ch) = v;
    }

    float accS[16][4];
    float accP[8][4], accR[8][4];
#pragma unroll
    for (int nt = 0; nt < 8; nt++)
#pragma unroll
        for (int q = 0; q < 4; q++) { accP[nt][q] = 0.f; accR[nt][q] = 0.f; }
    float rs0 = 0.f, rs1 = 0.f;

    for (int it = 0; it < 9; it++) {
        const int n0 = it * 128;
        __syncthreads();  // prev iter's reads done; Km visible on iter 0

        // group 0: Kn + Vs tiles
#pragma unroll
        for (int i = 0; i < 8; i++) {
            int c = tid + i * 256;
            int row = c >> 4, ch = (c & 15) * 4;
            int tok = n0 + row;
            int ok = (tok < NTOK);
            const float* src = Kbh + (size_t)(ok ? tok : 0) * HD + ch;
            cpasync16(smem_u32 + (SM_KN + row * LDK + ch) * 4, src, ok ? 16 : 0);
        }
#pragma unroll
        for (int i = 0; i < 8; i++) {
            int c = tid + i * 256;
            int row = c >> 4, ch = (c & 15) * 4;
            int tok = n0 + row;
            int ok = (tok < NTOK);
            const float* src = Vbh + (size_t)(ok ? tok : 0) * HD + ch;
            cpasync16(smem_u32 + (SM_VS + row * LDV + ch) * 4, src, ok ? 16 : 0);
        }
        asm volatile("cp.async.commit_group;");

        // group 1: rcs tile (waited only before GEMM2/3)
#pragma unroll
        for (int i = 0; i < 16; i++) {
            int c = tid + i * 256;
            int row = c >> 5, ch = (c & 31) * 4;
            int mm = m0 + row, nn = n0 + ch;
            int ok = (mm < NTOK) && (nn < NTOK);
            const float* src = Rbh + (size_t)(ok ? mm : 0) * NTOK + (ok ? nn : 0);
            cpasync16(smem_u32 + (SM_RB + row * LDR + ch) * 4, src, ok ? 16 : 0);
        }
        asm volatile("cp.async.commit_group;");

        asm volatile("cp.async.wait_group 1;");  // Kn, Vs ready
        __syncthreads();

        // ---- GEMM1: accS(16x128) = Km(16x64) . Kn^T ----
#pragma unroll
        for (int nt = 0; nt < 16; nt++)
#pragma unroll
            for (int q = 0; q < 4; q++) accS[nt][q] = 0.f;

#pragma unroll
        for (int ks = 0; ks < 8; ks++) {
            unsigned a0 = f2tf(Km[r0 * LDK + ks * 8 + t]);
            unsigned a1 = f2tf(Km[r1 * LDK + ks * 8 + t]);
            unsigned a2 = f2tf(Km[r0 * LDK + ks * 8 + t + 4]);
            unsigned a3 = f2tf(Km[r1 * LDK + ks * 8 + t + 4]);
#pragma unroll
            for (int nt = 0; nt < 16; nt++) {
                unsigned b0 = f2tf(Kn[(nt * 8 + g) * LDK + ks * 8 + t]);
                unsigned b1 = f2tf(Kn[(nt * 8 + g) * LDK + ks * 8 + t + 4]);
                mma_tf32(accS[nt], a0, a1, a2, a3, b0, b1);
            }
        }

        // ---- exp epilogue + rowsum partials ----
#pragma unroll
        for (int nt = 0; nt < 16; nt++) {
            int n = n0 + nt * 8 + 2 * t;       // even; n and n+1 valid together
            if (n < NTOK) {
                float ad0 = 0.f, ad1 = 0.f, bd0 = 0.f, bd1 = 0.f;
                if (gm0 < NTOK) {
                    float2 a = *(const float2*)(addn + (size_t)gm0 * NTOK + n);
                    ad0 = a.x; ad1 = a.y;
                }
                if (gm1 < NTOK) {
                    float2 a = *(const float2*)(addn + (size_t)gm1 * NTOK + n);
                    bd0 = a.x; bd1 = a.y;
                }
                float e0 = __expf(SCALE * accS[nt][0] + ad0);
                float e1 = __expf(SCALE * accS[nt][1] + ad1);
                float e2 = __expf(SCALE * accS[nt][2] + bd0);
                float e3 = __expf(SCALE * accS[nt][3] + bd1);
                accS[nt][0] = e0; accS[nt][1] = e1;
                accS[nt][2] = e2; accS[nt][3] = e3;
                rs0 += e0 + e1; rs1 += e2 + e3;
            } else {
                accS[nt][0] = 0.f; accS[nt][1] = 0.f;
                accS[nt][2] = 0.f; accS[nt][3] = 0.f;
            }
        }

        asm volatile("cp.async.wait_group 0;");  // rcs ready
        __syncthreads();

        // ---- fused GEMM2 (P@V) + GEMM3 (rcs@V) ----
        const int srcA = (lane & 28) | (t >> 1);
        const int srcB = srcA + 2;
        const bool odd = (t & 1);
#pragma unroll
        for (int ks = 0; ks < 16; ks++) {
            // C-layout -> A-layout conversion of the exp'd S subtile
            float c0 = accS[ks][0], c1 = accS[ks][1];
            float c2 = accS[ks][2], c3 = accS[ks][3];
            float x0 = __shfl_sync(0xffffffffu, c0, srcA);
            float x1 = __shfl_sync(0xffffffffu, c1, srcA);
            float y0 = __shfl_sync(0xffffffffu, c0, srcB);
            float y1 = __shfl_sync(0xffffffffu, c1, srcB);
            float w0 = __shfl_sync(0xffffffffu, c2, srcA);
            float w1 = __shfl_sync(0xffffffffu, c3, srcA);
            float u0 = __shfl_sync(0xffffffffu, c2, srcB);
            float u1 = __shfl_sync(0xffffffffu, c3, srcB);
            unsigned pa0 = f2tf(odd ? x1 : x0);
            unsigned pa1 = f2tf(odd ? w1 : w0);
            unsigned pa2 = f2tf(odd ? y1 : y0);
            unsigned pa3 = f2tf(odd ? u1 : u0);
            unsigned ra0 = f2tf(Rb[r0 * LDR + ks * 8 + t]);
            unsigned ra1 = f2tf(Rb[r1 * LDR + ks * 8 + t]);
            unsigned ra2 = f2tf(Rb[r0 * LDR + ks * 8 + t + 4]);
            unsigned ra3 = f2tf(Rb[r1 * LDR + ks * 8 + t + 4]);
#pragma unroll
            for (int nt = 0; nt < 8; nt++) {
                unsigned b0 = f2tf(Vs[(ks * 8 + t) * LDV + nt * 8 + g]);
                unsigned b1 = f2tf(Vs[(ks * 8 + t + 4) * LDV + nt * 8 + g]);
                mma_tf32(accP[nt], pa0, pa1, pa2, pa3, b0, b1);
                mma_tf32(accR[nt], ra0, ra1, ra2, ra3, b0, b1);
            }
        }
    }

    // ---- final epilogue: normalize + mix + store ----
    rs0 += __shfl_xor_sync(0xffffffffu, rs0, 1);
    rs0 += __shfl_xor_sync(0xffffffffu, rs0, 2);
    rs1 += __shfl_xor_sync(0xffffffffu, rs1, 1);
    rs1 += __shfl_xor_sync(0xffffffffu, rs1, 2);
    const float inv0 = W_SOFT / rs0, inv1 = W_SOFT / rs1;

    if (gm0 < NTOK) {
        float* op = g_O + ((size_t)b * NTOK + gm0) * C_ + hh * HD;
#pragma unroll
        for (int nt = 0; nt < 8; nt++) {
            int d = nt * 8 + 2 * t;
            float2 v = make_float2(accP[nt][0] * inv0 + W_RCS * accR[nt][0],
                                   accP[nt][1] * inv0 + W_RCS * accR[nt][1]);
            *(float2*)(op + d) = v;
        }
    }
    if (gm1 < NTOK) {
        float* op = g_O + ((size_t)b * NTOK + gm1) * C_ + hh * HD;
#pragma unroll
        for (int nt = 0; nt < 8; nt++) {
            int d = nt * 8 + 2 * t;
            float2 v = make_float2(accP[nt][2] * inv1 + W_RCS * accR[nt][2],
                                   accP[nt][3] * inv1 + W_RCS * accR[nt][3]);
            *(float2*)(op + d) = v;
        }
    }
}

// ---------------------------------------------------------------------------
// Kernel 3: out = g_O @ proj_w^T + proj_b   (tf32 mma).
// ---------------------------------------------------------------------------
__global__ __launch_bounds__(256) void proj_kernel(
    const float* __restrict__ proj_w, const float* __restrict__ proj_b,
    float* __restrict__ out)
{
    __shared__ unsigned As[128 * LDA];
    __shared__ unsigned Bs[128 * LDA];
    const int tid = threadIdx.x;
    const int m0 = blockIdx.y * 128, j0 = blockIdx.x * 128;
    const int wid = tid >> 5, lane = tid & 31;
    const int g = lane >> 2, t = lane & 3;
    const int wm = (wid >> 2) * 64, wn = (wid & 3) * 32;
    const int lrow = tid >> 1, lcol = (tid & 1) * 8;

    float acc[4][4][4];
#pragma unroll
    for (int a = 0; a < 4; a++)
#pragma unroll
        for (int b = 0; b < 4; b++)
#pragma unroll
            for (int c = 0; c < 4; c++) acc[a][b][c] = 0.f;

    for (int k0 = 0; k0 < C_; k0 += 16) {
        float4 v0, v1;
        if (m0 + lrow < M_ALL) {
            const float* p = g_O + (size_t)(m0 + lrow) * C_ + k0 + lcol;
            v0 = *(const float4*)p; v1 = *(const float4*)(p + 4);
        } else { v0 = make_float4(0,0,0,0); v1 = v0; }
        unsigned* a = As + lrow * LDA + lcol;
        a[0]=f2tf(v0.x); a[1]=f2tf(v0.y); a[2]=f2tf(v0.z); a[3]=f2tf(v0.w);
        a[4]=f2tf(v1.x); a[5]=f2tf(v1.y); a[6]=f2tf(v1.z); a[7]=f2tf(v1.w);

        const float* q = proj_w + (size_t)(j0 + lrow) * C_ + k0 + lcol;
        v0 = *(const float4*)q; v1 = *(const float4*)(q + 4);
        unsigned* bsp = Bs + lrow * LDA + lcol;
        bsp[0]=f2tf(v0.x); bsp[1]=f2tf(v0.y); bsp[2]=f2tf(v0.z); bsp[3]=f2tf(v0.w);
        bsp[4]=f2tf(v1.x); bsp[5]=f2tf(v1.y); bsp[6]=f2tf(v1.z); bsp[7]=f2tf(v1.w);
        __syncthreads();

#pragma unroll
        for (int ks = 0; ks < 16; ks += 8) {
            unsigned af[4][4], bf[4][2];
#pragma unroll
            for (int mt = 0; mt < 4; mt++) {
                const unsigned* ap = As + (wm + mt*16 + g) * LDA + ks + t;
                af[mt][0]=ap[0]; af[mt][1]=ap[8*LDA]; af[mt][2]=ap[4]; af[mt][3]=ap[8*LDA+4];
            }
#pragma unroll
            for (int nt = 0; nt < 4; nt++) {
                const unsigned* bp = Bs + (wn + nt*8 + g) * LDA + ks + t;
                bf[nt][0]=bp[0]; bf[nt][1]=bp[4];
            }
#pragma unroll
            for (int mt = 0; mt < 4; mt++)
#pragma unroll
                for (int nt = 0; nt < 4; nt++)
                    mma_tf32(acc[mt][nt], af[mt][0],af[mt][1],af[mt][2],af[mt][3],
                             bf[nt][0], bf[nt][1]);
        }
        __syncthreads();
    }

#pragma unroll
    for (int mt = 0; mt < 4; mt++) {
#pragma unroll
        for (int h = 0; h < 2; h++) {
            int m = m0 + wm + mt*16 + g + h*8;
            if (m >= M_ALL) continue;
#pragma unroll
            for (int nt = 0; nt < 4; nt++) {
                int j = j0 + wn + nt*8 + t*2;
                float2 v = make_float2(acc[mt][nt][h*2+0] + proj_b[j],
                                       acc[mt][nt][h*2+1] + proj_b[j+1]);
                *(float2*)(out + (size_t)m * C_ + j) = v;
            }
        }
    }
}

// ---------------------------------------------------------------------------
extern "C" void kernel_launch(void* const* d_in, const int* in_sizes, int n_in,
                              void* d_out, int out_size)
{
    const float* x      = (const float*)d_in[0];
    const float* qkv_w  = (const float*)d_in[1];
    const float* qkv_b  = (const float*)d_in[2];
    const float* proj_w = (const float*)d_in[3];
    const float* proj_b = (const float*)d_in[4];
    const float* addn   = (const float*)d_in[5];
    const float* rcs    = (const float*)d_in[6];
    float* out = (float*)d_out;

    cudaFuncSetAttribute(attn_fused_kernel,
                         cudaFuncAttributeMaxDynamicSharedMemorySize,
                         SMEM_WORDS * 4);

    kv_proj_kernel<<<dim3(16, 33), 256>>>(x, qkv_w, qkv_b);
    attn_fused_kernel<<<dim3(9, 64), 256, SMEM_WORDS * 4>>>(addn, rcs);
    proj_kernel<<<dim3(8, 33), 256>>>(proj_w, proj_b, out);
}

// round 6
// speedup vs baseline: 1.3225x; 1.3225x over previous
#include <cuda_runtime.h>
#include <cstdint>
#include <math.h>

// Problem constants
#define B_    4
#define NTOK  1032
#define C_    1024
#define H_    16
#define HD    64
#define BH    64            // B_*H_
#define M_ALL 4128          // B_*NTOK
#define SCALE 0.125f        // HD^-0.5
#define W_SOFT 0.8f         // TAU*(1-LAMBDA)
#define W_RCS  1.2f         // TAU*LAMBDA

#define LDA 20              // kv/proj smem row stride (words): 16 + 4 pad

// Fused-attention smem layout (32-bit words)
#define LDK 68
#define LDV 72
#define LDR 68
#define A_KN (128 * LDK)            // 8704
#define A_VS (A_KN + 64 * LDK)      // 13056
#define A_RB (A_VS + 64 * LDV)      // 17664
#define ATT_WORDS (A_RB + 128 * LDR)// 26368 words = 105472 bytes

// Scratch — K/V/O stored as tf32 bit patterns (pre-converted)
__device__ unsigned g_K[BH * NTOK * HD];
__device__ unsigned g_V[BH * NTOK * HD];
__device__ unsigned g_O[(size_t)M_ALL * C_];

__device__ __forceinline__ unsigned f2tf(float f) {
    unsigned u; asm("cvt.rna.tf32.f32 %0, %1;" : "=r"(u) : "f"(f)); return u;
}
__device__ __forceinline__ void mma_tf32(float* c, unsigned a0, unsigned a1,
                                         unsigned a2, unsigned a3,
                                         unsigned b0, unsigned b1) {
    asm volatile(
        "mma.sync.aligned.m16n8k8.row.col.f32.tf32.tf32.f32 "
        "{%0,%1,%2,%3},{%4,%5,%6,%7},{%8,%9},{%0,%1,%2,%3};"
        : "+f"(c[0]), "+f"(c[1]), "+f"(c[2]), "+f"(c[3])
        : "r"(a0), "r"(a1), "r"(a2), "r"(a3), "r"(b0), "r"(b1));
}
__device__ __forceinline__ void cpasync16(uint32_t dst, const void* src, int sbytes) {
    asm volatile("cp.async.cg.shared.global [%0], [%1], 16, %2;"
                 :: "r"(dst), "l"(src), "r"(sbytes));
}

// ---------------------------------------------------------------------------
// Kernel 1: K,V projection. Double-buffered cp.async pipeline, tf32 mma.
// BM=128 BN=128 BK=16, 8 warps 2x4, epilogue stores tf32 bits to g_K/g_V.
// ---------------------------------------------------------------------------
__global__ __launch_bounds__(256) void kv_proj_kernel(
    const float* __restrict__ x, const float* __restrict__ qkv_w,
    const float* __restrict__ qkv_b)
{
    __shared__ float As[2][128 * LDA];
    __shared__ float Bs[2][128 * LDA];
    const int tid = threadIdx.x;
    const int m0 = blockIdx.y * 128, j0 = blockIdx.x * 128;
    const int wid = tid >> 5, lane = tid & 31;
    const int g = lane >> 2, t = lane & 3;
    const int wm = (wid >> 2) * 64, wn = (wid & 3) * 32;
    const int lrow = tid >> 1, lcol = (tid & 1) * 8;
    const float* Wk = qkv_w + (size_t)C_ * C_;

    const int aok = (m0 + lrow < M_ALL) ? 16 : 0;
    const float* ax = x + (size_t)((m0 + lrow < M_ALL) ? (m0 + lrow) : 0) * C_ + lcol;
    const float* bx = Wk + (size_t)(j0 + lrow) * C_ + lcol;
    const uint32_t adst = (uint32_t)__cvta_generic_to_shared(As) + (lrow * LDA + lcol) * 4;
    const uint32_t bdst = (uint32_t)__cvta_generic_to_shared(Bs) + (lrow * LDA + lcol) * 4;
    const uint32_t stgB = 128 * LDA * 4;

#define KV_PREF(k0, s) do { \
    cpasync16(adst + (s) * stgB, ax + (k0), aok); \
    cpasync16(adst + (s) * stgB + 16, ax + (k0) + 4, aok); \
    cpasync16(bdst + (s) * stgB, bx + (k0), 16); \
    cpasync16(bdst + (s) * stgB + 16, bx + (k0) + 4, 16); \
    asm volatile("cp.async.commit_group;"); } while (0)

    float acc[4][4][4];
#pragma unroll
    for (int a = 0; a < 4; a++)
#pragma unroll
        for (int b = 0; b < 4; b++)
#pragma unroll
            for (int c = 0; c < 4; c++) acc[a][b][c] = 0.f;

    KV_PREF(0, 0);
    for (int kt = 0; kt < 64; kt++) {
        const int cur = kt & 1;
        if (kt < 63) {
            KV_PREF((kt + 1) * 16, (kt + 1) & 1);
            asm volatile("cp.async.wait_group 1;");
        } else {
            asm volatile("cp.async.wait_group 0;");
        }
        __syncthreads();
        const float* Af = As[cur];
        const float* Bf = Bs[cur];
#pragma unroll
        for (int ks = 0; ks < 16; ks += 8) {
            unsigned af[4][4], bf[4][2];
#pragma unroll
            for (int mt = 0; mt < 4; mt++) {
                const float* ap = Af + (wm + mt * 16 + g) * LDA + ks + t;
                af[mt][0] = f2tf(ap[0]);        af[mt][1] = f2tf(ap[8 * LDA]);
                af[mt][2] = f2tf(ap[4]);        af[mt][3] = f2tf(ap[8 * LDA + 4]);
            }
#pragma unroll
            for (int nt = 0; nt < 4; nt++) {
                const float* bp = Bf + (wn + nt * 8 + g) * LDA + ks + t;
                bf[nt][0] = f2tf(bp[0]);        bf[nt][1] = f2tf(bp[4]);
            }
#pragma unroll
            for (int mt = 0; mt < 4; mt++)
#pragma unroll
                for (int nt = 0; nt < 4; nt++)
                    mma_tf32(acc[mt][nt], af[mt][0], af[mt][1], af[mt][2], af[mt][3],
                             bf[nt][0], bf[nt][1]);
        }
        __syncthreads();
    }
#undef KV_PREF

#pragma unroll
    for (int mt = 0; mt < 4; mt++) {
#pragma unroll
        for (int h = 0; h < 2; h++) {
            int m = m0 + wm + mt * 16 + g + h * 8;
            if (m >= M_ALL) continue;
            int b = m / NTOK, n = m - b * NTOK;
#pragma unroll
            for (int nt = 0; nt < 4; nt++) {
                int j = j0 + wn + nt * 8 + t * 2;
#pragma unroll
                for (int c = 0; c < 2; c++) {
                    int jj = j + c;
                    unsigned uv = f2tf(acc[mt][nt][h * 2 + c] + qkv_b[C_ + jj]);
                    if (jj < C_) {
                        int hh = jj >> 6, d = jj & 63;
                        g_K[(((size_t)b * H_ + hh) * NTOK + n) * HD + d] = uv;
                    } else {
                        int j2 = jj - C_;
                        int hh = j2 >> 6, d = j2 & 63;
                        g_V[(((size_t)b * H_ + hh) * NTOK + n) * HD + d] = uv;
                    }
                }
            }
        }
    }
}

// ---------------------------------------------------------------------------
// Kernel 2: fused attention. Block = (bh, 128 m-rows), n-tile 64, 17 iters.
// 103 KB smem -> 2 CTAs/SM. K/V tiles arrive as tf32 bits (no cvt in GEMMs).
// ---------------------------------------------------------------------------
__global__ __launch_bounds__(256, 2) void attn_fused_kernel(
    const float* __restrict__ addn, const float* __restrict__ rcs)
{
    extern __shared__ unsigned smu[];
    unsigned* Km = smu;
    unsigned* Kn = smu + A_KN;
    unsigned* Vs = smu + A_VS;
    float*    Rb = (float*)(smu + A_RB);
    const int tid = threadIdx.x;
    const int bh = blockIdx.y;
    const int b = bh >> 4, hh = bh & 15;
    const int m0 = blockIdx.x * 128;
    const int wid = tid >> 5, lane = tid & 31;
    const int g = lane >> 2, t = lane & 3;
    const int r0 = wid * 16 + g;
    const int r1 = r0 + 8;
    const int gm0 = m0 + r0, gm1 = m0 + r1;
    const unsigned* Kbh = g_K + (size_t)bh * NTOK * HD;
    const unsigned* Vbh = g_V + (size_t)bh * NTOK * HD;
    const float* Rbh = rcs + (size_t)bh * NTOK * NTOK;
    const float* ad0p = addn + (size_t)(gm0 < NTOK ? gm0 : 0) * NTOK;
    const float* ad1p = addn + (size_t)(gm1 < NTOK ? gm1 : 0) * NTOK;

    const uint32_t su = (uint32_t)__cvta_generic_to_shared(smu);

    // Km fill (128 x 64 tf32 words)
#pragma unroll
    for (int i = 0; i < 8; i++) {
        int c = tid + i * 256;
        int row = c >> 4, ch = (c & 15) * 4;
        uint4 v = make_uint4(0u, 0u, 0u, 0u);
        if (m0 + row < NTOK)
            v = *(const uint4*)(Kbh + (size_t)(m0 + row) * HD + ch);
        *(uint4*)(Km + row * LDK + ch) = v;
    }

    float accS[8][4];
    float accP[8][4], accR[8][4];
#pragma unroll
    for (int nt = 0; nt < 8; nt++)
#pragma unroll
        for (int q = 0; q < 4; q++) { accP[nt][q] = 0.f; accR[nt][q] = 0.f; }
    float rs0 = 0.f, rs1 = 0.f;

    for (int it = 0; it < 17; it++) {
        const int n0 = it * 64;
        __syncthreads();  // smem reuse barrier; Km visible on it=0

        // group 0: Kn + Vs (64 rows each)
#pragma unroll
        for (int i = 0; i < 4; i++) {
            int c = tid + i * 256;
            int row = c >> 4, ch = (c & 15) * 4;
            int tok = n0 + row;
            int ok = (tok < NTOK);
            cpasync16(su + (A_KN + row * LDK + ch) * 4,
                      Kbh + (size_t)(ok ? tok : 0) * HD + ch, ok ? 16 : 0);
        }
#pragma unroll
        for (int i = 0; i < 4; i++) {
            int c = tid + i * 256;
            int row = c >> 4, ch = (c & 15) * 4;
            int tok = n0 + row;
            int ok = (tok < NTOK);
            cpasync16(su + (A_VS + row * LDV + ch) * 4,
                      Vbh + (size_t)(ok ? tok : 0) * HD + ch, ok ? 16 : 0);
        }
        asm volatile("cp.async.commit_group;");

        // group 1: rcs tile (128 x 64 fp32)
#pragma unroll
        for (int i = 0; i < 8; i++) {
            int c = tid + i * 256;
            int row = c >> 4, ch = (c & 15) * 4;
            int mm = m0 + row, nn = n0 + ch;
            int ok = (mm < NTOK) && (nn < NTOK);
            cpasync16(su + (A_RB + row * LDR + ch) * 4,
                      Rbh + (size_t)(ok ? mm : 0) * NTOK + (ok ? nn : 0), ok ? 16 : 0);
        }
        asm volatile("cp.async.commit_group;");

        asm volatile("cp.async.wait_group 1;");
        __syncthreads();

        // ---- GEMM1: accS(16x64) = Km . Kn^T ----
#pragma unroll
        for (int nt = 0; nt < 8; nt++)
#pragma unroll
            for (int q = 0; q < 4; q++) accS[nt][q] = 0.f;

#pragma unroll
        for (int ks = 0; ks < 8; ks++) {
            unsigned a0 = Km[r0 * LDK + ks * 8 + t];
            unsigned a1 = Km[r1 * LDK + ks * 8 + t];
            unsigned a2 = Km[r0 * LDK + ks * 8 + t + 4];
            unsigned a3 = Km[r1 * LDK + ks * 8 + t + 4];
#pragma unroll
            for (int nt = 0; nt < 8; nt++) {
                unsigned b0 = Kn[(nt * 8 + g) * LDK + ks * 8 + t];
                unsigned b1 = Kn[(nt * 8 + g) * LDK + ks * 8 + t + 4];
                mma_tf32(accS[nt], a0, a1, a2, a3, b0, b1);
            }
        }

        // ---- exp epilogue + rowsum partials ----
#pragma unroll
        for (int nt = 0; nt < 8; nt++) {
            int n = n0 + nt * 8 + 2 * t;
            if (n < NTOK) {
                float e0 = 0.f, e1 = 0.f, e2 = 0.f, e3 = 0.f;
                if (gm0 < NTOK) {
                    float2 a = *(const float2*)(ad0p + n);
                    e0 = __expf(SCALE * accS[nt][0] + a.x);
                    e1 = __expf(SCALE * accS[nt][1] + a.y);
                }
                if (gm1 < NTOK) {
                    float2 a = *(const float2*)(ad1p + n);
                    e2 = __expf(SCALE * accS[nt][2] + a.x);
                    e3 = __expf(SCALE * accS[nt][3] + a.y);
                }
                accS[nt][0] = e0; accS[nt][1] = e1;
                accS[nt][2] = e2; accS[nt][3] = e3;
                rs0 += e0 + e1; rs1 += e2 + e3;
            } else {
                accS[nt][0] = 0.f; accS[nt][1] = 0.f;
                accS[nt][2] = 0.f; accS[nt][3] = 0.f;
            }
        }

        asm volatile("cp.async.wait_group 0;");
        __syncthreads();

        // ---- fused GEMM2 (P@V) + GEMM3 (rcs@V) ----
        const int srcA = (lane & 28) | (t >> 1);
        const int srcB = srcA + 2;
        const bool odd = (t & 1);
#pragma unroll
        for (int ks = 0; ks < 8; ks++) {
            float c0 = accS[ks][0], c1 = accS[ks][1];
            float c2 = accS[ks][2], c3 = accS[ks][3];
            float x0 = __shfl_sync(0xffffffffu, c0, srcA);
            float x1 = __shfl_sync(0xffffffffu, c1, srcA);
            float y0 = __shfl_sync(0xffffffffu, c0, srcB);
            float y1 = __shfl_sync(0xffffffffu, c1, srcB);
            float w0 = __shfl_sync(0xffffffffu, c2, srcA);
            float w1 = __shfl_sync(0xffffffffu, c3, srcA);
            float u0 = __shfl_sync(0xffffffffu, c2, srcB);
            float u1 = __shfl_sync(0xffffffffu, c3, srcB);
            unsigned pa0 = f2tf(odd ? x1 : x0);
            unsigned pa1 = f2tf(odd ? w1 : w0);
            unsigned pa2 = f2tf(odd ? y1 : y0);
            unsigned pa3 = f2tf(odd ? u1 : u0);
            unsigned ra0 = f2tf(Rb[r0 * LDR + ks * 8 + t]);
            unsigned ra1 = f2tf(Rb[r1 * LDR + ks * 8 + t]);
            unsigned ra2 = f2tf(Rb[r0 * LDR + ks * 8 + t + 4]);
            unsigned ra3 = f2tf(Rb[r1 * LDR + ks * 8 + t + 4]);
#pragma unroll
            for (int nt = 0; nt < 8; nt++) {
                unsigned b0 = Vs[(ks * 8 + t) * LDV + nt * 8 + g];
                unsigned b1 = Vs[(ks * 8 + t + 4) * LDV + nt * 8 + g];
                mma_tf32(accP[nt], pa0, pa1, pa2, pa3, b0, b1);
                mma_tf32(accR[nt], ra0, ra1, ra2, ra3, b0, b1);
            }
        }
    }

    // ---- final epilogue: normalize + mix + store tf32 bits to g_O ----
    rs0 += __shfl_xor_sync(0xffffffffu, rs0, 1);
    rs0 += __shfl_xor_sync(0xffffffffu, rs0, 2);
    rs1 += __shfl_xor_sync(0xffffffffu, rs1, 1);
    rs1 += __shfl_xor_sync(0xffffffffu, rs1, 2);
    const float inv0 = W_SOFT / rs0, inv1 = W_SOFT / rs1;

    if (gm0 < NTOK) {
        unsigned* op = g_O + ((size_t)b * NTOK + gm0) * C_ + hh * HD;
#pragma unroll
        for (int nt = 0; nt < 8; nt++) {
            int d = nt * 8 + 2 * t;
            uint2 v;
            v.x = f2tf(accP[nt][0] * inv0 + W_RCS * accR[nt][0]);
            v.y = f2tf(accP[nt][1] * inv0 + W_RCS * accR[nt][1]);
            *(uint2*)(op + d) = v;
        }
    }
    if (gm1 < NTOK) {
        unsigned* op = g_O + ((size_t)b * NTOK + gm1) * C_ + hh * HD;
#pragma unroll
        for (int nt = 0; nt < 8; nt++) {
            int d = nt * 8 + 2 * t;
            uint2 v;
            v.x = f2tf(accP[nt][2] * inv1 + W_RCS * accR[nt][2]);
            v.y = f2tf(accP[nt][3] * inv1 + W_RCS * accR[nt][3]);
            *(uint2*)(op + d) = v;
        }
    }
}

// ---------------------------------------------------------------------------
// Kernel 3: out = g_O @ proj_w^T + proj_b. Double-buffered cp.async, tf32 mma.
// A operand (g_O) already tf32 bits — no cvt.
// ---------------------------------------------------------------------------
__global__ __launch_bounds__(256) void proj_kernel(
    const float* __restrict__ proj_w, const float* __restrict__ proj_b,
    float* __restrict__ out)
{
    __shared__ unsigned As[2][128 * LDA];
    __shared__ float    Bs[2][128 * LDA];
    const int tid = threadIdx.x;
    const int m0 = blockIdx.y * 128, j0 = blockIdx.x * 128;
    const int wid = tid >> 5, lane = tid & 31;
    const int g = lane >> 2, t = lane & 3;
    const int wm = (wid >> 2) * 64, wn = (wid & 3) * 32;
    const int lrow = tid >> 1, lcol = (tid & 1) * 8;

    const int aok = (m0 + lrow < M_ALL) ? 16 : 0;
    const unsigned* ax = g_O + (size_t)((m0 + lrow < M_ALL) ? (m0 + lrow) : 0) * C_ + lcol;
    const float* bx = proj_w + (size_t)(j0 + lrow) * C_ + lcol;
    const uint32_t adst = (uint32_t)__cvta_generic_to_shared(As) + (lrow * LDA + lcol) * 4;
    const uint32_t bdst = (uint32_t)__cvta_generic_to_shared(Bs) + (lrow * LDA + lcol) * 4;
    const uint32_t stgB = 128 * LDA * 4;

#define PJ_PREF(k0, s) do { \
    cpasync16(adst + (s) * stgB, ax + (k0), aok); \
    cpasync16(adst + (s) * stgB + 16, ax + (k0) + 4, aok); \
    cpasync16(bdst + (s) * stgB, bx + (k0), 16); \
    cpasync16(bdst + (s) * stgB + 16, bx + (k0) + 4, 16); \
    asm volatile("cp.async.commit_group;"); } while (0)

    float acc[4][4][4];
#pragma unroll
    for (int a = 0; a < 4; a++)
#pragma unroll
        for (int b = 0; b < 4; b++)
#pragma unroll
            for (int c = 0; c < 4; c++) acc[a][b][c] = 0.f;

    PJ_PREF(0, 0);
    for (int kt = 0; kt < 64; kt++) {
        const int cur = kt & 1;
        if (kt < 63) {
            PJ_PREF((kt + 1) * 16, (kt + 1) & 1);
            asm volatile("cp.async.wait_group 1;");
        } else {
            asm volatile("cp.async.wait_group 0;");
        }
        __syncthreads();
        const unsigned* Au = As[cur];
        const float* Bf = Bs[cur];
#pragma unroll
        for (int ks = 0; ks < 16; ks += 8) {
            unsigned af[4][4], bf[4][2];
#pragma unroll
            for (int mt = 0; mt < 4; mt++) {
                const unsigned* ap = Au + (wm + mt * 16 + g) * LDA + ks + t;
                af[mt][0] = ap[0];       af[mt][1] = ap[8 * LDA];
                af[mt][2] = ap[4];       af[mt][3] = ap[8 * LDA + 4];
            }
#pragma unroll
            for (int nt = 0; nt < 4; nt++) {
                const float* bp = Bf + (wn + nt * 8 + g) * LDA + ks + t;
                bf[nt][0] = f2tf(bp[0]); bf[nt][1] = f2tf(bp[4]);
            }
#pragma unroll
            for (int mt = 0; mt < 4; mt++)
#pragma unroll
                for (int nt = 0; nt < 4; nt++)
                    mma_tf32(acc[mt][nt], af[mt][0], af[mt][1], af[mt][2], af[mt][3],
                             bf[nt][0], bf[nt][1]);
        }
        __syncthreads();
    }
#undef PJ_PREF

#pragma unroll
    for (int mt = 0; mt < 4; mt++) {
#pragma unroll
        for (int h = 0; h < 2; h++) {
            int m = m0 + wm + mt * 16 + g + h * 8;
            if (m >= M_ALL) continue;
#pragma unroll
            for (int nt = 0; nt < 4; nt++) {
                int j = j0 + wn + nt * 8 + t * 2;
                float2 v = make_float2(acc[mt][nt][h * 2 + 0] + proj_b[j],
                                       acc[mt][nt][h * 2 + 1] + proj_b[j + 1]);
                *(float2*)(out + (size_t)m * C_ + j) = v;
            }
        }
    }
}

// ---------------------------------------------------------------------------
extern "C" void kernel_launch(void* const* d_in, const int* in_sizes, int n_in,
                              void* d_out, int out_size)
{
    const float* x      = (const float*)d_in[0];
    const float* qkv_w  = (const float*)d_in[1];
    const float* qkv_b  = (const float*)d_in[2];
    const float* proj_w = (const float*)d_in[3];
    const float* proj_b = (const float*)d_in[4];
    const float* addn   = (const float*)d_in[5];
    const float* rcs    = (const float*)d_in[6];
    float* out = (float*)d_out;

    cudaFuncSetAttribute(attn_fused_kernel,
                         cudaFuncAttributeMaxDynamicSharedMemorySize,
                         ATT_WORDS * 4);

    kv_proj_kernel<<<dim3(16, 33), 256>>>(x, qkv_w, qkv_b);
    attn_fused_kernel<<<dim3(9, 64), 256, ATT_WORDS * 4>>>(addn, rcs);
    proj_kernel<<<dim3(8, 33), 256>>>(proj_w, proj_b, out);
}